// round 12
// baseline (speedup 1.0000x reference)
#include <cuda_runtime.h>
#include <math.h>

#define NCLS 19
#define DD   128
#define HWP  65536          // H*W
#define BB   8
#define NPIX (BB*HWP)       // 524288

#define P1_BLOCKS  592              // 4 x 148 SMs, single wave
#define P1_THREADS 288              // 8 MMA warps (dims) + 1 label warp
#define P1_CHUNK   128              // pixels per chunk (8 ksteps)
#define P1_NCHUNK  (NPIX/P1_CHUNK)  // 4096

#define P2_THREADS 256
#define P2_PXB     512              // pixels per block (2 px per thread)
#define P2_BLOCKS  (NPIX/P2_PXB)    // 1024

// ---- static scratch (no allocations allowed; zero-init at load) ----
__device__ float          g_sums[NCLS*DD];
__device__ int            g_cnt[NCLS];
__device__ float          g_var[NCLS];
__device__ unsigned int   g_done2;
__device__ unsigned char  g_labs[NPIX];

// ---------------------------------------------------------------- pass 1
// Segment-sum as GEMM: D[d][c] = sum_p feats[d][p] * onehot(lab[p]==c).
// Warps 0..7: mma.sync.m16n8k16, A = feats [16 dims x 16 px] bf16 loaded
// straight from global in fragment layout (__ldcs, zero reuse), B = onehot
// built in registers from raw int32 labels, C = fp32 [16 d x 24 cls]
// accumulated across all chunks; single atomic writeout.
// Warp 8: reads raw labels (int4), histograms into g_cnt, packs g_labs.
__global__ void __launch_bounds__(P1_THREADS, 4) k_pass1(const float* __restrict__ feats,
                                                         const int* __restrict__ labels) {
    __shared__ int hist[NCLS];
    int w    = threadIdx.x >> 5;
    int lane = threadIdx.x & 31;

    if (w == 8) {
        // ---------------- label warp: histogram + pack ----------------
        if (lane < NCLS) hist[lane] = 0;
        __syncwarp();
        for (int ch = blockIdx.x; ch < P1_NCHUNK; ch += P1_BLOCKS) {
            int pxg = ch * P1_CHUNK;
            int4 lv = ((const int4*)(labels + pxg))[lane];   // 4 labels/lane
            uchar4 u;
            u.x = (lv.x >= 0 && lv.x < NCLS) ? (unsigned char)lv.x : (unsigned char)255;
            u.y = (lv.y >= 0 && lv.y < NCLS) ? (unsigned char)lv.y : (unsigned char)255;
            u.z = (lv.z >= 0 && lv.z < NCLS) ? (unsigned char)lv.z : (unsigned char)255;
            u.w = (lv.w >= 0 && lv.w < NCLS) ? (unsigned char)lv.w : (unsigned char)255;
            ((uchar4*)(g_labs + pxg))[lane] = u;
            if (u.x < NCLS) atomicAdd(&hist[u.x], 1);
            if (u.y < NCLS) atomicAdd(&hist[u.y], 1);
            if (u.z < NCLS) atomicAdd(&hist[u.z], 1);
            if (u.w < NCLS) atomicAdd(&hist[u.w], 1);
        }
        __syncwarp();
        if (lane < NCLS) atomicAdd(&g_cnt[lane], hist[lane]);
        return;
    }

    // ---------------- MMA warps: segment-sum GEMM ----------------
    int gid  = lane >> 2;            // 0..7
    int ktid = lane & 3;             // 0..3
    int d_lo = w*16 + gid;

    float c0[4] = {0.f,0.f,0.f,0.f};
    float c1[4] = {0.f,0.f,0.f,0.f};
    float c2[4] = {0.f,0.f,0.f,0.f};

    for (int ch = blockIdx.x; ch < P1_NCHUNK; ch += P1_BLOCKS) {
        int pxg = ch * P1_CHUNK;         // plane-aligned: 128 | 65536
        int b   = pxg >> 16;
        int po  = pxg & 65535;
        const float* rowA = feats + ((size_t)b*DD + d_lo    ) * HWP + po;
        const float* rowB = feats + ((size_t)b*DD + d_lo + 8) * HWP + po;
        const int*   labp = labels + pxg;

        #pragma unroll 2
        for (int ks = 0; ks < P1_CHUNK/16; ks++) {
            int p0 = ks*16 + 2*ktid;     // thread's k-anchor within the 16-px tile
            float2 fa0 = __ldcs((const float2*)(rowA + p0));        // A[gid][k0,k0+1]
            float2 fa1 = __ldcs((const float2*)(rowB + p0));        // A[gid+8][k0,k0+1]
            float2 fa2 = __ldcs((const float2*)(rowA + p0 + 8));    // A[gid][k0+8,k0+9]
            float2 fa3 = __ldcs((const float2*)(rowB + p0 + 8));    // A[gid+8][k0+8,k0+9]
            unsigned a0, a1, a2, a3;
            asm("cvt.rn.bf16x2.f32 %0, %1, %2;" : "=r"(a0) : "f"(fa0.y), "f"(fa0.x));
            asm("cvt.rn.bf16x2.f32 %0, %1, %2;" : "=r"(a1) : "f"(fa1.y), "f"(fa1.x));
            asm("cvt.rn.bf16x2.f32 %0, %1, %2;" : "=r"(a2) : "f"(fa2.y), "f"(fa2.x));
            asm("cvt.rn.bf16x2.f32 %0, %1, %2;" : "=r"(a3) : "f"(fa3.y), "f"(fa3.x));

            int2 L01 = *(const int2*)(labp + p0);       // L1/L2 hit (8 warps share)
            int2 L89 = *(const int2*)(labp + p0 + 8);
            int l0 = L01.x, l1 = L01.y;
            int l8 = L89.x, l9 = L89.y;

            {   int cls = gid;                       // tile 0: classes 0..7
                unsigned b0 = (l0==cls ? 0x3F80u : 0u) | (l1==cls ? 0x3F800000u : 0u);
                unsigned b1 = (l8==cls ? 0x3F80u : 0u) | (l9==cls ? 0x3F800000u : 0u);
                asm("mma.sync.aligned.m16n8k16.row.col.f32.bf16.bf16.f32 "
                    "{%0,%1,%2,%3}, {%4,%5,%6,%7}, {%8,%9}, {%0,%1,%2,%3};"
                    : "+f"(c0[0]), "+f"(c0[1]), "+f"(c0[2]), "+f"(c0[3])
                    : "r"(a0), "r"(a1), "r"(a2), "r"(a3), "r"(b0), "r"(b1));
            }
            {   int cls = gid + 8;                   // tile 1: classes 8..15
                unsigned b0 = (l0==cls ? 0x3F80u : 0u) | (l1==cls ? 0x3F800000u : 0u);
                unsigned b1 = (l8==cls ? 0x3F80u : 0u) | (l9==cls ? 0x3F800000u : 0u);
                asm("mma.sync.aligned.m16n8k16.row.col.f32.bf16.bf16.f32 "
                    "{%0,%1,%2,%3}, {%4,%5,%6,%7}, {%8,%9}, {%0,%1,%2,%3};"
                    : "+f"(c1[0]), "+f"(c1[1]), "+f"(c1[2]), "+f"(c1[3])
                    : "r"(a0), "r"(a1), "r"(a2), "r"(a3), "r"(b0), "r"(b1));
            }
            {   int cls = gid + 16;                  // tile 2: classes 16..23
                unsigned b0 = (l0==cls ? 0x3F80u : 0u) | (l1==cls ? 0x3F800000u : 0u);
                unsigned b1 = (l8==cls ? 0x3F80u : 0u) | (l9==cls ? 0x3F800000u : 0u);
                asm("mma.sync.aligned.m16n8k16.row.col.f32.bf16.bf16.f32 "
                    "{%0,%1,%2,%3}, {%4,%5,%6,%7}, {%8,%9}, {%0,%1,%2,%3};"
                    : "+f"(c2[0]), "+f"(c2[1]), "+f"(c2[2]), "+f"(c2[3])
                    : "r"(a0), "r"(a1), "r"(a2), "r"(a3), "r"(b0), "r"(b1));
            }
        }
    }

    // writeout: C[m][n] -> d = w*16 + m (m = gid, gid+8), cls = 8t + n
    int dA = w*16 + gid, dB = dA + 8;
    {   int n0 = 2*ktid, n1 = n0 + 1;             // tile 0: cls 0..7
        atomicAdd(&g_sums[n0*DD + dA], c0[0]);
        atomicAdd(&g_sums[n1*DD + dA], c0[1]);
        atomicAdd(&g_sums[n0*DD + dB], c0[2]);
        atomicAdd(&g_sums[n1*DD + dB], c0[3]);
    }
    {   int n0 = 8 + 2*ktid, n1 = n0 + 1;         // tile 1: cls 8..15
        atomicAdd(&g_sums[n0*DD + dA], c1[0]);
        atomicAdd(&g_sums[n1*DD + dA], c1[1]);
        atomicAdd(&g_sums[n0*DD + dB], c1[2]);
        atomicAdd(&g_sums[n1*DD + dB], c1[3]);
    }
    {   int n0 = 16 + 2*ktid, n1 = n0 + 1;        // tile 2: cls 16..23 (keep <19)
        if (n0 < NCLS) { atomicAdd(&g_sums[n0*DD + dA], c2[0]);
                         atomicAdd(&g_sums[n0*DD + dB], c2[2]); }
        if (n1 < NCLS) { atomicAdd(&g_sums[n1*DD + dA], c2[1]);
                         atomicAdd(&g_sums[n1*DD + dB], c2[3]); }
    }
}

// ---------------------------------------------------------------- pass 2
// Each thread owns a PIXEL PAIR (float2 loads; a warp covers 64 contiguous
// px = 256B per plane) and walks d in 16 iterations loading 8 planes
// concurrently (d, d+16, ..., d+112) -> 8 loads in flight per thread
// (~114KB outstanding per SM; Little's law for ~8TB/s).
// Means in shared at stride 129 (distinct labels -> distinct banks).
// 1024 blocks, 7/SM -> single wave. Last block assembles the loss.
__global__ void __launch_bounds__(P2_THREADS, 7) k_pass2(const float* __restrict__ feats,
                                                         float* __restrict__ out) {
    __shared__ float ms[NCLS*129];
    __shared__ float vs[NCLS];
    int t = threadIdx.x;
    for (int i = t; i < NCLS*DD; i += P2_THREADS) {
        int c = i >> 7;
        ms[c*129 + (i & 127)] = g_sums[i] / fmaxf((float)g_cnt[c], 1.f);
    }
    if (t < NCLS) vs[t] = 0.f;
    __syncthreads();

    int px = blockIdx.x*P2_PXB + 2*t;      // even; block is plane-aligned (512 | 65536)
    int b  = px >> 16;
    int po = px & 65535;
    const float* fb = feats + (size_t)b*DD*HWP + po;   // plane d at fb + d*HWP

    uchar2 l2 = *(const uchar2*)(g_labs + px);
    int l0 = l2.x, l1 = l2.y;
    const float* mr0 = ms + (l0 < NCLS ? l0 : 0)*129;
    const float* mr1 = ms + (l1 < NCLS ? l1 : 0)*129;

    float acc0 = 0.f, acc1 = 0.f;
    for (int d = 0; d < 16; d++) {
        float2 v0 = *(const float2*)(fb + (size_t)(d      )*HWP);
        float2 v1 = *(const float2*)(fb + (size_t)(d +  16)*HWP);
        float2 v2 = *(const float2*)(fb + (size_t)(d +  32)*HWP);
        float2 v3 = *(const float2*)(fb + (size_t)(d +  48)*HWP);
        float2 v4 = *(const float2*)(fb + (size_t)(d +  64)*HWP);
        float2 v5 = *(const float2*)(fb + (size_t)(d +  80)*HWP);
        float2 v6 = *(const float2*)(fb + (size_t)(d +  96)*HWP);
        float2 v7 = *(const float2*)(fb + (size_t)(d + 112)*HWP);
        float df;
        df = v0.x - mr0[d      ]; acc0 = fmaf(df, df, acc0);
        df = v1.x - mr0[d +  16]; acc0 = fmaf(df, df, acc0);
        df = v2.x - mr0[d +  32]; acc0 = fmaf(df, df, acc0);
        df = v3.x - mr0[d +  48]; acc0 = fmaf(df, df, acc0);
        df = v4.x - mr0[d +  64]; acc0 = fmaf(df, df, acc0);
        df = v5.x - mr0[d +  80]; acc0 = fmaf(df, df, acc0);
        df = v6.x - mr0[d +  96]; acc0 = fmaf(df, df, acc0);
        df = v7.x - mr0[d + 112]; acc0 = fmaf(df, df, acc0);
        df = v0.y - mr1[d      ]; acc1 = fmaf(df, df, acc1);
        df = v1.y - mr1[d +  16]; acc1 = fmaf(df, df, acc1);
        df = v2.y - mr1[d +  32]; acc1 = fmaf(df, df, acc1);
        df = v3.y - mr1[d +  48]; acc1 = fmaf(df, df, acc1);
        df = v4.y - mr1[d +  64]; acc1 = fmaf(df, df, acc1);
        df = v5.y - mr1[d +  80]; acc1 = fmaf(df, df, acc1);
        df = v6.y - mr1[d +  96]; acc1 = fmaf(df, df, acc1);
        df = v7.y - mr1[d + 112]; acc1 = fmaf(df, df, acc1);
    }
    if (l0 < NCLS) { float h = fmaxf(sqrtf(acc0) - 0.5f, 0.f); atomicAdd(&vs[l0], h*h); }
    if (l1 < NCLS) { float h = fmaxf(sqrtf(acc1) - 0.5f, 0.f); atomicAdd(&vs[l1], h*h); }
    __syncthreads();
    if (t < NCLS) atomicAdd(&g_var[t], vs[t]);

    // ---- last-arriving block: final loss assembly + scratch reset ----
    __threadfence();
    __shared__ bool isLast;
    if (t == 0) isLast = (atomicAdd(&g_done2, 1u) == P2_BLOCKS - 1);
    __syncthreads();
    if (!isLast) return;

    __shared__ float vld[NCLS];
    __shared__ float sreg[NCLS];
    __shared__ float spair[NCLS*NCLS];
    if (t < NCLS) {
        vld[t] = (g_cnt[t] > 100) ? 1.f : 0.f;   // MAX_VIEWS = 100, strict >
        float s = 0.f;
        #pragma unroll 16
        for (int d = 0; d < DD; d++) { float m = ms[t*129 + d]; s = fmaf(m, m, s); }
        sreg[t] = (s > 0.f) ? sqrtf(s) : 0.f;
    }
    for (int idx = t; idx < NCLS*NCLS; idx += P2_THREADS) {
        int a = idx / NCLS, b2 = idx % NCLS;
        float s = 0.f;
        #pragma unroll 16
        for (int d = 0; d < DD; d++) {
            float diff = ms[a*129 + d] - ms[b2*129 + d];
            s = fmaf(diff, diff, s);
        }
        float pdn = (s > 0.f) ? sqrtf(s) : 0.f;
        float hd  = fmaxf(2.f*1.5f - pdn, 0.f);   // 2*DELTA_D
        spair[idx] = hd*hd;
    }
    // reset g_sums for next replay (all pass2 reads of g_sums are done)
    for (int i = t; i < NCLS*DD; i += P2_THREADS) g_sums[i] = 0.f;
    __syncthreads();
    if (t == 0) {
        int last = -1;
        for (int c = 0; c < NCLS; c++) if (vld[c] > 0.f) last = c;
        float tc = 0.f, lvar = 0.f, lreg = 0.f, ldist = 0.f;
        for (int c = 0; c < NCLS; c++) {
            if (vld[c] > 0.f) {
                tc   += 1.f;
                lvar += g_var[c] / fmaxf((float)g_cnt[c], 1.f);
                lreg += sreg[c];
            }
        }
        // faithful buggy double loop: a over all valid, b over valid except
        // the LAST valid class id; includes a == b pairs.
        for (int a = 0; a < NCLS; a++)
            for (int b2 = 0; b2 < NCLS; b2++)
                if (vld[a] > 0.f && vld[b2] > 0.f && b2 != last)
                    ldist += spair[a*NCLS + b2];
        out[0] = lvar/tc + ldist/(tc*(tc - 1.f)) + 0.001f*lreg/tc;  // ALPHA=BETA=1, GAMMA=1e-3
        // reset for next replay (g_cnt is re-accumulated by pass1)
        for (int c = 0; c < NCLS; c++) { g_var[c] = 0.f; g_cnt[c] = 0; }
        g_done2 = 0u;
    }
}

// ---------------------------------------------------------------- launch
extern "C" void kernel_launch(void* const* d_in, const int* in_sizes, int n_in,
                              void* d_out, int out_size) {
    const float* feats  = (const float*)d_in[0];
    const int*   labels = (const int*)d_in[1];
    float* out = (float*)d_out;

    k_pass1<<<P1_BLOCKS, P1_THREADS>>>(feats, labels);
    k_pass2<<<P2_BLOCKS, P2_THREADS>>>(feats, out);
}